// round 3
// baseline (speedup 1.0000x reference)
#include <cuda_runtime.h>

// 8-point DCT-II basis as compile-time constants -> FFMA immediates after unroll.
__device__ constexpr float D8[8][8] = {
  { 0.35355339059327373f, 0.35355339059327373f, 0.35355339059327373f, 0.35355339059327373f,
    0.35355339059327373f, 0.35355339059327373f, 0.35355339059327373f, 0.35355339059327373f},
  { 0.49039264020161522f, 0.41573480615127262f, 0.27778511650980114f, 0.09754516100806417f,
   -0.09754516100806417f,-0.27778511650980114f,-0.41573480615127262f,-0.49039264020161522f},
  { 0.46193976625564337f, 0.19134171618254492f,-0.19134171618254492f,-0.46193976625564337f,
   -0.46193976625564337f,-0.19134171618254492f, 0.19134171618254492f, 0.46193976625564337f},
  { 0.41573480615127262f,-0.09754516100806417f,-0.49039264020161522f,-0.27778511650980114f,
    0.27778511650980114f, 0.49039264020161522f, 0.09754516100806417f,-0.41573480615127262f},
  { 0.35355339059327379f,-0.35355339059327379f,-0.35355339059327379f, 0.35355339059327379f,
    0.35355339059327379f,-0.35355339059327379f,-0.35355339059327379f, 0.35355339059327379f},
  { 0.27778511650980114f,-0.49039264020161522f, 0.09754516100806417f, 0.41573480615127262f,
   -0.41573480615127262f,-0.09754516100806417f, 0.49039264020161522f,-0.27778511650980114f},
  { 0.19134171618254492f,-0.46193976625564337f, 0.46193976625564337f,-0.19134171618254492f,
   -0.19134171618254492f, 0.46193976625564337f,-0.46193976625564337f, 0.19134171618254492f},
  { 0.09754516100806417f,-0.27778511650980114f, 0.41573480615127262f,-0.49039264020161522f,
    0.49039264020161522f,-0.41573480615127262f, 0.27778511650980114f,-0.09754516100806417f}
};

__constant__ float QYc[64] = {
  16,11,10,16,24,40,51,61,
  12,12,14,19,26,58,60,55,
  14,13,16,24,40,57,69,56,
  14,17,22,29,51,87,80,62,
  18,22,37,56,68,109,103,77,
  24,35,55,64,81,104,113,92,
  49,64,78,87,103,121,120,101,
  72,92,95,98,112,100,103,99
};
__constant__ float QCc[64] = {
  17,18,24,47,99,99,99,99,
  18,21,26,66,99,99,99,99,
  24,26,56,99,99,99,99,99,
  47,66,99,99,99,99,99,99,
  99,99,99,99,99,99,99,99,
  99,99,99,99,99,99,99,99,
  99,99,99,99,99,99,99,99,
  99,99,99,99,99,99,99,99
};

#define QFACTOR 0.5f

// Tile: 32 rows x 64 cols. 48 blocks of 8x8 in shared scratch:
//   blk 0..31  : Y   (blk = (row>>3)*8 + (col>>3))
//   blk 32..39 : Cb  (16x32 downsampled, blk = 32 + (crow>>3)*4 + (ccol>>3))
//   blk 40..47 : Cr
// s[blk*72 + x*9 + y]: row stride 9, block stride 72 -> conflict-free scalar
// access in both row and column orientation.

__global__ __launch_bounds__(512, 3) void diffjpeg_kernel(
    const float* __restrict__ x, float* __restrict__ out)
{
    __shared__ float s[48 * 72];
    __shared__ float2 qYp[64], qCp[64];   // (q, 1/q)

    const int tid = threadIdx.x;
    if (tid < 64) {
        const float a = QYc[tid] * QFACTOR;
        const float b = QCc[tid] * QFACTOR;
        qYp[tid] = make_float2(a, 1.0f / a);
        qCp[tid] = make_float2(b, 1.0f / b);
    }

    const int bz = blockIdx.z;      // batch 0..15
    const int tr = blockIdx.y;      // tile row 0..15 (32 rows each)
    const int tc = blockIdx.x;      // tile col 0..7  (64 cols each)
    const size_t plane4 = 512 * 512 / 4;     // plane size in float4
    const float4* px4 = (const float4*)x   + (size_t)bz * 3 * plane4 + (size_t)(tr * 32) * 128 + tc * 16;
    float4*       po4 = (float4*)out       + (size_t)bz * 3 * plane4 + (size_t)(tr * 32) * 128 + tc * 16;

    // ---- Phase 1: vector load, clip, RGB->YCbCr, chroma 2x2 downsample ----
    {
        const int row = tid >> 4;   // 0..31
        const int cg  = tid & 15;   // 0..15 -> cols 4cg..4cg+3
        const float4 R4 = px4[(size_t)row * 128 + cg];
        const float4 G4 = px4[plane4 + (size_t)row * 128 + cg];
        const float4 B4 = px4[2 * plane4 + (size_t)row * 128 + cg];
        float rr[4] = {R4.x, R4.y, R4.z, R4.w};
        float gg[4] = {G4.x, G4.y, G4.z, G4.w};
        float bb[4] = {B4.x, B4.y, B4.z, B4.w};
        float cbv[4], crv[4];
        float* bY = s + ((row >> 3) * 8 + (cg >> 1)) * 72 + (row & 7) * 9 + (cg & 1) * 4;
        #pragma unroll
        for (int j = 0; j < 4; ++j) {
            const float r1 = fminf(fmaxf(rr[j], 0.f), 1.f) * 255.f;
            const float g1 = fminf(fmaxf(gg[j], 0.f), 1.f) * 255.f;
            const float b1 = fminf(fmaxf(bb[j], 0.f), 1.f) * 255.f;
            bY[j] = 0.299f * r1 + 0.587f * g1 + 0.114f * b1 - 128.f;
            cbv[j] = -0.168736f * r1 - 0.331264f * g1 + 0.5f * b1;
            crv[j] =  0.5f * r1 - 0.418688f * g1 - 0.081312f * b1;
        }
        float cbh[2] = {cbv[0] + cbv[1], cbv[2] + cbv[3]};
        float crh[2] = {crv[0] + crv[1], crv[2] + crv[3]};
        #pragma unroll
        for (int k = 0; k < 2; ++k) {
            cbh[k] += __shfl_xor_sync(0xffffffffu, cbh[k], 16);
            crh[k] += __shfl_xor_sync(0xffffffffu, crh[k], 16);
        }
        if ((tid & 16) == 0) {      // even row of the vertical pair
            const int crow = row >> 1;           // 0..15
            const int base = (crow & 7) * 9;
            #pragma unroll
            for (int k = 0; k < 2; ++k) {
                const int ccol = 2 * cg + k;     // 0..31
                const int cblk = 32 + (crow >> 3) * 4 + (ccol >> 3);
                s[cblk * 72 + base + (ccol & 7)]       = 0.25f * cbh[k];
                s[(cblk + 8) * 72 + base + (ccol & 7)] = 0.25f * crh[k];
            }
        }
    }
    __syncthreads();

    // ---- Pass A: forward DCT along y (contiguous dir). One thread per block-row. ----
    if (tid < 384) {
        const int blk = tid >> 3, xx = tid & 7;
        float* bp = s + blk * 72 + xx * 9;
        float in[8];
        #pragma unroll
        for (int j = 0; j < 8; ++j) in[j] = bp[j];
        #pragma unroll
        for (int v = 0; v < 8; ++v) {
            float t = 0.f;
            #pragma unroll
            for (int y = 0; y < 8; ++y) t += D8[v][y] * in[y];
            bp[v] = t;
        }
    }
    __syncthreads();

    // ---- Pass B: forward DCT along x + quantize + inverse DCT along x ----
    if (tid < 384) {
        const int blk = tid >> 3, v = tid & 7;
        float* bp = s + blk * 72 + v;
        const float2* qp = (blk < 32) ? qYp : qCp;
        float t[8], w[8];
        #pragma unroll
        for (int xx = 0; xx < 8; ++xx) { t[xx] = bp[xx * 9]; w[xx] = 0.f; }
        #pragma unroll
        for (int u = 0; u < 8; ++u) {
            float cf = 0.f;
            #pragma unroll
            for (int xx = 0; xx < 8; ++xx) cf += D8[u][xx] * t[xx];
            const float2 qq = qp[u * 8 + v];
            cf = rintf(cf * qq.y) * qq.x;   // round-half-even, matches jnp.round
            #pragma unroll
            for (int xx = 0; xx < 8; ++xx) w[xx] += D8[u][xx] * cf;
        }
        #pragma unroll
        for (int xx = 0; xx < 8; ++xx) bp[xx * 9] = w[xx];
    }
    __syncthreads();

    // ---- Pass C: inverse DCT along y. Y threads keep results in registers;
    //      chroma threads publish to shared for the output stage. ----
    float rec[8];
    if (tid < 384) {
        const int blk = tid >> 3, xx = tid & 7;
        float* bp = s + blk * 72 + xx * 9;
        float w[8];
        #pragma unroll
        for (int v = 0; v < 8; ++v) w[v] = bp[v];
        #pragma unroll
        for (int y = 0; y < 8; ++y) {
            float rv = 0.f;
            #pragma unroll
            for (int v = 0; v < 8; ++v) rv += D8[v][y] * w[v];
            rec[y] = rv;
        }
        if (blk >= 32) {
            #pragma unroll
            for (int y = 0; y < 8; ++y) bp[y] = rec[y];
        }
    }
    __syncthreads();

    // ---- Output: Y threads (tid<256) combine their register-resident Y row
    //      with reconstructed chroma, clip, and vector-store RGB. ----
    if (tid < 256) {
        const int blk = tid >> 3, xx = tid & 7;
        const int rb = blk >> 3, cbx = blk & 7;
        const int row = rb * 8 + xx;
        const int crow = row >> 1;
        const int base = (crow & 7) * 9;
        float cbm[4], crm[4];
        #pragma unroll
        for (int i = 0; i < 4; ++i) {
            const int ccol = cbx * 4 + i;
            const int cblk = (crow >> 3) * 4 + (ccol >> 3);
            const int eoff = base + (ccol & 7);
            cbm[i] = s[(32 + cblk) * 72 + eoff];
            crm[i] = s[(40 + cblk) * 72 + eoff];
        }
        float R[8], G[8], B[8];
        #pragma unroll
        for (int y = 0; y < 8; ++y) {
            const int i = y >> 1;
            const float yv = rec[y] + 128.f;
            float Rv = yv + 1.402f * crm[i];
            float Gv = yv - 0.344136f * cbm[i] - 0.714136f * crm[i];
            float Bv = yv + 1.772f * cbm[i];
            R[y] = fminf(fmaxf(Rv, 0.f), 255.f) * (1.0f / 255.0f);
            G[y] = fminf(fmaxf(Gv, 0.f), 255.f) * (1.0f / 255.0f);
            B[y] = fminf(fmaxf(Bv, 0.f), 255.f) * (1.0f / 255.0f);
        }
        const size_t o = (size_t)row * 128 + cbx * 2;
        po4[o]     = make_float4(R[0], R[1], R[2], R[3]);
        po4[o + 1] = make_float4(R[4], R[5], R[6], R[7]);
        po4[plane4 + o]     = make_float4(G[0], G[1], G[2], G[3]);
        po4[plane4 + o + 1] = make_float4(G[4], G[5], G[6], G[7]);
        po4[2 * plane4 + o]     = make_float4(B[0], B[1], B[2], B[3]);
        po4[2 * plane4 + o + 1] = make_float4(B[4], B[5], B[6], B[7]);
    }
}

extern "C" void kernel_launch(void* const* d_in, const int* in_sizes, int n_in,
                              void* d_out, int out_size)
{
    const float* x = (const float*)d_in[0];
    float* out = (float*)d_out;
    (void)in_sizes; (void)n_in; (void)out_size;
    dim3 grid(8, 16, 16);   // tile cols (512/64), tile rows (512/32), batch
    diffjpeg_kernel<<<grid, 512>>>(x, out);
}

// round 4
// speedup vs baseline: 1.1503x; 1.1503x over previous
#include <cuda_runtime.h>

// 8-point DCT-II basis as compile-time constants -> FFMA immediates after unroll.
__device__ constexpr float D8[8][8] = {
  { 0.35355339059327373f, 0.35355339059327373f, 0.35355339059327373f, 0.35355339059327373f,
    0.35355339059327373f, 0.35355339059327373f, 0.35355339059327373f, 0.35355339059327373f},
  { 0.49039264020161522f, 0.41573480615127262f, 0.27778511650980114f, 0.09754516100806417f,
   -0.09754516100806417f,-0.27778511650980114f,-0.41573480615127262f,-0.49039264020161522f},
  { 0.46193976625564337f, 0.19134171618254492f,-0.19134171618254492f,-0.46193976625564337f,
   -0.46193976625564337f,-0.19134171618254492f, 0.19134171618254492f, 0.46193976625564337f},
  { 0.41573480615127262f,-0.09754516100806417f,-0.49039264020161522f,-0.27778511650980114f,
    0.27778511650980114f, 0.49039264020161522f, 0.09754516100806417f,-0.41573480615127262f},
  { 0.35355339059327379f,-0.35355339059327379f,-0.35355339059327379f, 0.35355339059327379f,
    0.35355339059327379f,-0.35355339059327379f,-0.35355339059327379f, 0.35355339059327379f},
  { 0.27778511650980114f,-0.49039264020161522f, 0.09754516100806417f, 0.41573480615127262f,
   -0.41573480615127262f,-0.09754516100806417f, 0.49039264020161522f,-0.27778511650980114f},
  { 0.19134171618254492f,-0.46193976625564337f, 0.46193976625564337f,-0.19134171618254492f,
   -0.19134171618254492f, 0.46193976625564337f,-0.46193976625564337f, 0.19134171618254492f},
  { 0.09754516100806417f,-0.27778511650980114f, 0.41573480615127262f,-0.49039264020161522f,
    0.49039264020161522f,-0.41573480615127262f, 0.27778511650980114f,-0.09754516100806417f}
};

__constant__ float QYc[64] = {
  16,11,10,16,24,40,51,61,
  12,12,14,19,26,58,60,55,
  14,13,16,24,40,57,69,56,
  14,17,22,29,51,87,80,62,
  18,22,37,56,68,109,103,77,
  24,35,55,64,81,104,113,92,
  49,64,78,87,103,121,120,101,
  72,92,95,98,112,100,103,99
};
__constant__ float QCc[64] = {
  17,18,24,47,99,99,99,99,
  18,21,26,66,99,99,99,99,
  24,26,56,99,99,99,99,99,
  47,66,99,99,99,99,99,99,
  99,99,99,99,99,99,99,99,
  99,99,99,99,99,99,99,99,
  99,99,99,99,99,99,99,99,
  99,99,99,99,99,99,99,99
};

#define QFACTOR 0.5f

// Tile: 32 rows x 64 cols. 48 blocks of 8x8 in shared scratch:
//   blk 0..31  : Y   (blk = (row>>3)*8 + (col>>3))
//   blk 32..39 : Cb  (16x32 downsampled, blk = 32 + (crow>>3)*4 + (ccol>>3))
//   blk 40..47 : Cr
// s[blk*72 + x*9 + y]: row stride 9, block stride 72 -> conflict-free scalar
// access for the DCT passes in both orientations.

__global__ __launch_bounds__(512) void diffjpeg_kernel(
    const float* __restrict__ x, float* __restrict__ out)
{
    __shared__ float s[48 * 72];
    __shared__ float2 qYp[64], qCp[64];   // (q, 1/q)

    const int tid = threadIdx.x;
    if (tid < 64) {
        const float a = QYc[tid] * QFACTOR;
        const float b = QCc[tid] * QFACTOR;
        qYp[tid] = make_float2(a, 1.0f / a);
        qCp[tid] = make_float2(b, 1.0f / b);
    }

    const int bz = blockIdx.z;      // batch 0..15
    const int tr = blockIdx.y;      // tile row 0..15 (32 rows each)
    const int tc = blockIdx.x;      // tile col 0..7  (64 cols each)
    const size_t plane4 = 512 * 512 / 4;     // plane size in float4
    const float4* px4 = (const float4*)x + (size_t)bz * 3 * plane4 + (size_t)(tr * 32) * 128 + tc * 16;
    float4*       po4 = (float4*)out     + (size_t)bz * 3 * plane4 + (size_t)(tr * 32) * 128 + tc * 16;

    const int row = tid >> 4;   // 0..31
    const int cg  = tid & 15;   // 0..15 -> cols 4cg..4cg+3

    // ---- Phase 1: vector load, clip, RGB->YCbCr, chroma 2x2 downsample ----
    {
        const float4 R4 = px4[(size_t)row * 128 + cg];
        const float4 G4 = px4[plane4 + (size_t)row * 128 + cg];
        const float4 B4 = px4[2 * plane4 + (size_t)row * 128 + cg];
        float rr[4] = {R4.x, R4.y, R4.z, R4.w};
        float gg[4] = {G4.x, G4.y, G4.z, G4.w};
        float bb[4] = {B4.x, B4.y, B4.z, B4.w};
        float cbv[4], crv[4];
        float* bY = s + ((row >> 3) * 8 + (cg >> 1)) * 72 + (row & 7) * 9 + (cg & 1) * 4;
        #pragma unroll
        for (int j = 0; j < 4; ++j) {
            const float r1 = fminf(fmaxf(rr[j], 0.f), 1.f) * 255.f;
            const float g1 = fminf(fmaxf(gg[j], 0.f), 1.f) * 255.f;
            const float b1 = fminf(fmaxf(bb[j], 0.f), 1.f) * 255.f;
            bY[j] = 0.299f * r1 + 0.587f * g1 + 0.114f * b1 - 128.f;
            cbv[j] = -0.168736f * r1 - 0.331264f * g1 + 0.5f * b1;
            crv[j] =  0.5f * r1 - 0.418688f * g1 - 0.081312f * b1;
        }
        float cbh[2] = {cbv[0] + cbv[1], cbv[2] + cbv[3]};
        float crh[2] = {crv[0] + crv[1], crv[2] + crv[3]};
        #pragma unroll
        for (int k = 0; k < 2; ++k) {
            cbh[k] += __shfl_xor_sync(0xffffffffu, cbh[k], 16);
            crh[k] += __shfl_xor_sync(0xffffffffu, crh[k], 16);
        }
        if ((tid & 16) == 0) {      // even row of the vertical pair
            const int crow = row >> 1;           // 0..15
            const int base = (crow & 7) * 9;
            #pragma unroll
            for (int k = 0; k < 2; ++k) {
                const int ccol = 2 * cg + k;     // 0..31
                const int cblk = 32 + (crow >> 3) * 4 + (ccol >> 3);
                s[cblk * 72 + base + (ccol & 7)]       = 0.25f * cbh[k];   // no +128
                s[(cblk + 8) * 72 + base + (ccol & 7)] = 0.25f * crh[k];
            }
        }
    }
    __syncthreads();

    // ---- Pass A: forward DCT along y (contiguous dir). One thread per block-row. ----
    if (tid < 384) {
        const int blk = tid >> 3, xx = tid & 7;
        float* bp = s + blk * 72 + xx * 9;
        float in[8];
        #pragma unroll
        for (int j = 0; j < 8; ++j) in[j] = bp[j];
        #pragma unroll
        for (int v = 0; v < 8; ++v) {
            float t = 0.f;
            #pragma unroll
            for (int y = 0; y < 8; ++y) t += D8[v][y] * in[y];
            bp[v] = t;
        }
    }
    __syncthreads();

    // ---- Pass B: forward DCT along x + quantize + inverse DCT along x ----
    if (tid < 384) {
        const int blk = tid >> 3, v = tid & 7;
        float* bp = s + blk * 72 + v;
        const float2* qp = (blk < 32) ? qYp : qCp;
        float t[8], w[8];
        #pragma unroll
        for (int xx = 0; xx < 8; ++xx) { t[xx] = bp[xx * 9]; w[xx] = 0.f; }
        #pragma unroll
        for (int u = 0; u < 8; ++u) {
            float cf = 0.f;
            #pragma unroll
            for (int xx = 0; xx < 8; ++xx) cf += D8[u][xx] * t[xx];
            const float2 qq = qp[u * 8 + v];
            cf = rintf(cf * qq.y) * qq.x;   // round-half-even, matches jnp.round
            #pragma unroll
            for (int xx = 0; xx < 8; ++xx) w[xx] += D8[u][xx] * cf;
        }
        #pragma unroll
        for (int xx = 0; xx < 8; ++xx) bp[xx * 9] = w[xx];
    }
    __syncthreads();

    // ---- Pass C: inverse DCT along y, write back to shared ----
    if (tid < 384) {
        const int blk = tid >> 3, xx = tid & 7;
        float* bp = s + blk * 72 + xx * 9;
        float w[8];
        #pragma unroll
        for (int v = 0; v < 8; ++v) w[v] = bp[v];
        #pragma unroll
        for (int y = 0; y < 8; ++y) {
            float rv = 0.f;
            #pragma unroll
            for (int v = 0; v < 8; ++v) rv += D8[v][y] * w[v];
            bp[y] = rv;
        }
    }
    __syncthreads();

    // ---- Output: all 512 threads. Same mapping as phase 1: row, 4 cols.
    //      Upsample chroma, YCbCr->RGB, clip, /255, vector store. ----
    {
        const float* bY = s + ((row >> 3) * 8 + (cg >> 1)) * 72 + (row & 7) * 9 + (cg & 1) * 4;
        const int crow = row >> 1;
        const int base = (crow & 7) * 9;
        const int ccol0 = 2 * cg;                // even; ccol0 and ccol0+1 same block
        const int cblk = 32 + (crow >> 3) * 4 + (ccol0 >> 3);
        const float cb0 = s[cblk * 72 + base + (ccol0 & 7)];
        const float cb1 = s[cblk * 72 + base + (ccol0 & 7) + 1];
        const float cr0 = s[(cblk + 8) * 72 + base + (ccol0 & 7)];
        const float cr1 = s[(cblk + 8) * 72 + base + (ccol0 & 7) + 1];
        const float cbm[4] = {cb0, cb0, cb1, cb1};
        const float crm[4] = {cr0, cr0, cr1, cr1};
        float R[4], G[4], B[4];
        #pragma unroll
        for (int j = 0; j < 4; ++j) {
            const float yv = bY[j] + 128.f;
            float Rv = yv + 1.402f * crm[j];
            float Gv = yv - 0.344136f * cbm[j] - 0.714136f * crm[j];
            float Bv = yv + 1.772f * cbm[j];
            R[j] = fminf(fmaxf(Rv, 0.f), 255.f) * (1.0f / 255.0f);
            G[j] = fminf(fmaxf(Gv, 0.f), 255.f) * (1.0f / 255.0f);
            B[j] = fminf(fmaxf(Bv, 0.f), 255.f) * (1.0f / 255.0f);
        }
        const size_t o = (size_t)row * 128 + cg;
        po4[o]               = make_float4(R[0], R[1], R[2], R[3]);
        po4[plane4 + o]      = make_float4(G[0], G[1], G[2], G[3]);
        po4[2 * plane4 + o]  = make_float4(B[0], B[1], B[2], B[3]);
    }
}

extern "C" void kernel_launch(void* const* d_in, const int* in_sizes, int n_in,
                              void* d_out, int out_size)
{
    const float* x = (const float*)d_in[0];
    float* out = (float*)d_out;
    (void)in_sizes; (void)n_in; (void)out_size;
    dim3 grid(8, 16, 16);   // tile cols (512/64), tile rows (512/32), batch
    diffjpeg_kernel<<<grid, 512>>>(x, out);
}

// round 6
// speedup vs baseline: 1.2618x; 1.0970x over previous
#include <cuda_runtime.h>

// 8-point DCT-II basis as compile-time constants -> FFMA immediates after unroll.
__device__ constexpr float D8[8][8] = {
  { 0.35355339059327373f, 0.35355339059327373f, 0.35355339059327373f, 0.35355339059327373f,
    0.35355339059327373f, 0.35355339059327373f, 0.35355339059327373f, 0.35355339059327373f},
  { 0.49039264020161522f, 0.41573480615127262f, 0.27778511650980114f, 0.09754516100806417f,
   -0.09754516100806417f,-0.27778511650980114f,-0.41573480615127262f,-0.49039264020161522f},
  { 0.46193976625564337f, 0.19134171618254492f,-0.19134171618254492f,-0.46193976625564337f,
   -0.46193976625564337f,-0.19134171618254492f, 0.19134171618254492f, 0.46193976625564337f},
  { 0.41573480615127262f,-0.09754516100806417f,-0.49039264020161522f,-0.27778511650980114f,
    0.27778511650980114f, 0.49039264020161522f, 0.09754516100806417f,-0.41573480615127262f},
  { 0.35355339059327379f,-0.35355339059327379f,-0.35355339059327379f, 0.35355339059327379f,
    0.35355339059327379f,-0.35355339059327379f,-0.35355339059327379f, 0.35355339059327379f},
  { 0.27778511650980114f,-0.49039264020161522f, 0.09754516100806417f, 0.41573480615127262f,
   -0.41573480615127262f,-0.09754516100806417f, 0.49039264020161522f,-0.27778511650980114f},
  { 0.19134171618254492f,-0.46193976625564337f, 0.46193976625564337f,-0.19134171618254492f,
   -0.19134171618254492f, 0.46193976625564337f,-0.46193976625564337f, 0.19134171618254492f},
  { 0.09754516100806417f,-0.27778511650980114f, 0.41573480615127262f,-0.49039264020161522f,
    0.49039264020161522f,-0.41573480615127262f, 0.27778511650980114f,-0.09754516100806417f}
};

__constant__ float QYc[64] = {
  16,11,10,16,24,40,51,61,
  12,12,14,19,26,58,60,55,
  14,13,16,24,40,57,69,56,
  14,17,22,29,51,87,80,62,
  18,22,37,56,68,109,103,77,
  24,35,55,64,81,104,113,92,
  49,64,78,87,103,121,120,101,
  72,92,95,98,112,100,103,99
};
__constant__ float QCc[64] = {
  17,18,24,47,99,99,99,99,
  18,21,26,66,99,99,99,99,
  24,26,56,99,99,99,99,99,
  47,66,99,99,99,99,99,99,
  99,99,99,99,99,99,99,99,
  99,99,99,99,99,99,99,99,
  99,99,99,99,99,99,99,99,
  99,99,99,99,99,99,99,99
};

#define QFACTOR 0.5f

// Forward 8-pt DCT with even/odd fold. in8 -> out8. 8 ADD + 32 FMA.
#define DCT_FWD_FOLD(in8, out8)                                            \
  {                                                                        \
    float e_[4], o_[4];                                                    \
    _Pragma("unroll")                                                      \
    for (int j_ = 0; j_ < 4; ++j_) {                                       \
      e_[j_] = in8[j_] + in8[7 - j_];                                      \
      o_[j_] = in8[j_] - in8[7 - j_];                                      \
    }                                                                      \
    _Pragma("unroll")                                                      \
    for (int v_ = 0; v_ < 8; v_ += 2) {                                    \
      float se_ = 0.f, so_ = 0.f;                                          \
      _Pragma("unroll")                                                    \
      for (int j_ = 0; j_ < 4; ++j_) {                                     \
        se_ += D8[v_][j_] * e_[j_];                                        \
        so_ += D8[v_ + 1][j_] * o_[j_];                                    \
      }                                                                    \
      out8[v_] = se_; out8[v_ + 1] = so_;                                  \
    }                                                                      \
  }

// Inverse 8-pt DCT with fold. w8 -> rec8. 32 FMA + 8 ADD.
#define DCT_INV_FOLD(w8, rec8)                                             \
  {                                                                        \
    _Pragma("unroll")                                                      \
    for (int j_ = 0; j_ < 4; ++j_) {                                       \
      float E_ = 0.f, O_ = 0.f;                                            \
      _Pragma("unroll")                                                    \
      for (int v_ = 0; v_ < 8; v_ += 2) {                                  \
        E_ += D8[v_][j_] * w8[v_];                                         \
        O_ += D8[v_ + 1][j_] * w8[v_ + 1];                                 \
      }                                                                    \
      rec8[j_] = E_ + O_; rec8[7 - j_] = E_ - O_;                          \
    }                                                                      \
  }

// Tile: 32 rows x 64 cols. 48 blocks of 8x8 in shared scratch:
//   blk 0..31  : Y   (blk = (row>>3)*8 + (col>>3))
//   blk 32..39 : Cb  (16x32 downsampled), blk 40..47 : Cr
//   -> chroma = 16 blocks = 128 row-units
// s[blk*72 + x*9 + y]: conflict-free for the x-direction pass.

__global__ __launch_bounds__(512) void diffjpeg_kernel(
    const float* __restrict__ x, float* __restrict__ out)
{
    __shared__ float s[48 * 72];
    __shared__ float2 qYp[64], qCp[64];   // (q, 1/q)

    const int tid = threadIdx.x;
    if (tid < 64) {
        const float a = QYc[tid] * QFACTOR;
        const float b = QCc[tid] * QFACTOR;
        qYp[tid] = make_float2(a, 1.0f / a);
        qCp[tid] = make_float2(b, 1.0f / b);
    }

    const int bz = blockIdx.z;
    const int tr = blockIdx.y;
    const int tc = blockIdx.x;
    const size_t plane4 = 512 * 512 / 4;
    const float4* px4 = (const float4*)x + (size_t)bz * 3 * plane4 + (size_t)(tr * 32) * 128 + tc * 16;
    float4*       po4 = (float4*)out     + (size_t)bz * 3 * plane4 + (size_t)(tr * 32) * 128 + tc * 16;

    const int row = tid >> 4;   // 0..31
    const int cg  = tid & 15;   // 0..15 -> cols 4cg..4cg+3
    const bool hi = (cg & 1);   // which half of the 8-col block this thread owns
    const int yblk = (row >> 3) * 8 + (cg >> 1);
    float* bYv = s + yblk * 72 + (row & 7) * 9;   // block row base (freq index appended)

    // ---- Phase 1: load, clip, RGB->YCbCr, Y forward-y DCT (regs+shfl),
    //      chroma 2x2 downsample ----
    {
        const float4 R4 = px4[(size_t)row * 128 + cg];
        const float4 G4 = px4[plane4 + (size_t)row * 128 + cg];
        const float4 B4 = px4[2 * plane4 + (size_t)row * 128 + cg];
        float rr[4] = {R4.x, R4.y, R4.z, R4.w};
        float gg[4] = {G4.x, G4.y, G4.z, G4.w};
        float bb[4] = {B4.x, B4.y, B4.z, B4.w};
        float yv[4], cbv[4], crv[4];
        #pragma unroll
        for (int j = 0; j < 4; ++j) {
            const float r1 = fminf(fmaxf(rr[j], 0.f), 1.f) * 255.f;
            const float g1 = fminf(fmaxf(gg[j], 0.f), 1.f) * 255.f;
            const float b1 = fminf(fmaxf(bb[j], 0.f), 1.f) * 255.f;
            yv[j] = 0.299f * r1 + 0.587f * g1 + 0.114f * b1 - 128.f;
            cbv[j] = -0.168736f * r1 - 0.331264f * g1 + 0.5f * b1;
            crv[j] =  0.5f * r1 - 0.418688f * g1 - 0.081312f * b1;
        }
        // gather the full 8-pixel block row: partner lane is lane^1 (same row, cg^1)
        float ov[4];
        #pragma unroll
        for (int j = 0; j < 4; ++j) ov[j] = __shfl_xor_sync(0xffffffffu, yv[j], 1);
        float in8[8];
        #pragma unroll
        for (int j = 0; j < 4; ++j) {
            in8[j]     = hi ? ov[j] : yv[j];
            in8[4 + j] = hi ? yv[j] : ov[j];
        }
        float out8[8];
        DCT_FWD_FOLD(in8, out8);
        #pragma unroll
        for (int j = 0; j < 4; ++j)
            bYv[(hi ? 4 : 0) + j] = hi ? out8[4 + j] : out8[j];

        // chroma: horizontal pair in-thread, vertical pair via shfl xor 16
        float cbh[2] = {cbv[0] + cbv[1], cbv[2] + cbv[3]};
        float crh[2] = {crv[0] + crv[1], crv[2] + crv[3]};
        #pragma unroll
        for (int k = 0; k < 2; ++k) {
            cbh[k] += __shfl_xor_sync(0xffffffffu, cbh[k], 16);
            crh[k] += __shfl_xor_sync(0xffffffffu, crh[k], 16);
        }
        if ((tid & 16) == 0) {
            const int crow = row >> 1;
            const int base = (crow & 7) * 9;
            #pragma unroll
            for (int k = 0; k < 2; ++k) {
                const int ccol = 2 * cg + k;
                const int cblk = 32 + (crow >> 3) * 4 + (ccol >> 3);
                s[cblk * 72 + base + (ccol & 7)]       = 0.25f * cbh[k];
                s[(cblk + 8) * 72 + base + (ccol & 7)] = 0.25f * crh[k];
            }
        }
    }
    __syncthreads();

    // ---- Region 2: Y pass-B on threads 0..255; chroma chain on 256..511 ----
    if (tid < 256) {
        // Y blocks: 32 blocks x 8 columns = 256 units
        const int blk = tid >> 3, v = tid & 7;
        float* bp = s + blk * 72 + v;
        float t[8];
        #pragma unroll
        for (int xx = 0; xx < 8; ++xx) t[xx] = bp[xx * 9];
        float cf[8];
        DCT_FWD_FOLD(t, cf);
        #pragma unroll
        for (int u = 0; u < 8; ++u) {
            const float2 qq = qYp[u * 8 + v];
            cf[u] = rintf(cf[u] * qq.y) * qq.x;   // round-half-even
        }
        float w[8];
        DCT_INV_FOLD(cf, w);
        #pragma unroll
        for (int xx = 0; xx < 8; ++xx) bp[xx * 9] = w[xx];
    } else {
        const int u = tid - 256;   // 0..255; chroma needs 128 units (16 blocks x 8)
        // (a) chroma forward DCT along y (stride-1 rows)
        if (u < 128) {
            const int blk = 32 + (u >> 3), xx = u & 7;
            float* bp = s + blk * 72 + xx * 9;
            float in8[8];
            #pragma unroll
            for (int j = 0; j < 8; ++j) in8[j] = bp[j];
            float out8[8];
            DCT_FWD_FOLD(in8, out8);
            #pragma unroll
            for (int j = 0; j < 8; ++j) bp[j] = out8[j];
        }
        asm volatile("bar.sync 1, 256;" ::: "memory");
        // (b) chroma pass-B along x (stride-9)
        if (u < 128) {
            const int blk = 32 + (u >> 3), v = u & 7;
            float* bp = s + blk * 72 + v;
            float t[8];
            #pragma unroll
            for (int xx = 0; xx < 8; ++xx) t[xx] = bp[xx * 9];
            float cf[8];
            DCT_FWD_FOLD(t, cf);
            #pragma unroll
            for (int uu = 0; uu < 8; ++uu) {
                const float2 qq = qCp[uu * 8 + v];
                cf[uu] = rintf(cf[uu] * qq.y) * qq.x;
            }
            float w[8];
            DCT_INV_FOLD(cf, w);
            #pragma unroll
            for (int xx = 0; xx < 8; ++xx) bp[xx * 9] = w[xx];
        }
        asm volatile("bar.sync 1, 256;" ::: "memory");
        // (c) chroma inverse DCT along y
        if (u < 128) {
            const int blk = 32 + (u >> 3), xx = u & 7;
            float* bp = s + blk * 72 + xx * 9;
            float w[8];
            #pragma unroll
            for (int v = 0; v < 8; ++v) w[v] = bp[v];
            float rec[8];
            DCT_INV_FOLD(w, rec);
            #pragma unroll
            for (int j = 0; j < 8; ++j) bp[j] = rec[j];
        }
    }
    __syncthreads();

    // ---- Output: inverse-y for Y in registers + chroma upsample + store ----
    {
        float w[8];
        #pragma unroll
        for (int v = 0; v < 8; ++v) w[v] = bYv[v];
        float E[4], O[4];
        #pragma unroll
        for (int j = 0; j < 4; ++j) {
            float Ee = 0.f, Oo = 0.f;
            #pragma unroll
            for (int v = 0; v < 8; v += 2) {
                Ee += D8[v][j] * w[v];
                Oo += D8[v + 1][j] * w[v + 1];
            }
            E[j] = Ee; O[j] = Oo;
        }
        float yrec[4];
        #pragma unroll
        for (int j = 0; j < 4; ++j)
            yrec[j] = hi ? (E[3 - j] - O[3 - j]) : (E[j] + O[j]);

        const int crow = row >> 1;
        const int base = (crow & 7) * 9;
        const int ccol0 = 2 * cg;
        const int cblk = 32 + (crow >> 3) * 4 + (ccol0 >> 3);
        const float cb0 = s[cblk * 72 + base + (ccol0 & 7)];
        const float cb1 = s[cblk * 72 + base + (ccol0 & 7) + 1];
        const float cr0 = s[(cblk + 8) * 72 + base + (ccol0 & 7)];
        const float cr1 = s[(cblk + 8) * 72 + base + (ccol0 & 7) + 1];
        const float cbm[4] = {cb0, cb0, cb1, cb1};
        const float crm[4] = {cr0, cr0, cr1, cr1};
        float R[4], G[4], B[4];
        #pragma unroll
        for (int j = 0; j < 4; ++j) {
            const float yv = yrec[j] + 128.f;
            float Rv = yv + 1.402f * crm[j];
            float Gv = yv - 0.344136f * cbm[j] - 0.714136f * crm[j];
            float Bv = yv + 1.772f * cbm[j];
            R[j] = fminf(fmaxf(Rv, 0.f), 255.f) * (1.0f / 255.0f);
            G[j] = fminf(fmaxf(Gv, 0.f), 255.f) * (1.0f / 255.0f);
            B[j] = fminf(fmaxf(Bv, 0.f), 255.f) * (1.0f / 255.0f);
        }
        const size_t o = (size_t)row * 128 + cg;
        po4[o]              = make_float4(R[0], R[1], R[2], R[3]);
        po4[plane4 + o]     = make_float4(G[0], G[1], G[2], G[3]);
        po4[2 * plane4 + o] = make_float4(B[0], B[1], B[2], B[3]);
    }
}

extern "C" void kernel_launch(void* const* d_in, const int* in_sizes, int n_in,
                              void* d_out, int out_size)
{
    const float* x = (const float*)d_in[0];
    float* out = (float*)d_out;
    (void)in_sizes; (void)n_in; (void)out_size;
    dim3 grid(8, 16, 16);   // tile cols (512/64), tile rows (512/32), batch
    diffjpeg_kernel<<<grid, 512>>>(x, out);
}

// round 7
// speedup vs baseline: 1.2653x; 1.0028x over previous
#include <cuda_runtime.h>

// 8-point DCT-II basis as compile-time constants -> FFMA immediates after unroll.
__device__ constexpr float D8[8][8] = {
  { 0.35355339059327373f, 0.35355339059327373f, 0.35355339059327373f, 0.35355339059327373f,
    0.35355339059327373f, 0.35355339059327373f, 0.35355339059327373f, 0.35355339059327373f},
  { 0.49039264020161522f, 0.41573480615127262f, 0.27778511650980114f, 0.09754516100806417f,
   -0.09754516100806417f,-0.27778511650980114f,-0.41573480615127262f,-0.49039264020161522f},
  { 0.46193976625564337f, 0.19134171618254492f,-0.19134171618254492f,-0.46193976625564337f,
   -0.46193976625564337f,-0.19134171618254492f, 0.19134171618254492f, 0.46193976625564337f},
  { 0.41573480615127262f,-0.09754516100806417f,-0.49039264020161522f,-0.27778511650980114f,
    0.27778511650980114f, 0.49039264020161522f, 0.09754516100806417f,-0.41573480615127262f},
  { 0.35355339059327379f,-0.35355339059327379f,-0.35355339059327379f, 0.35355339059327379f,
    0.35355339059327379f,-0.35355339059327379f,-0.35355339059327379f, 0.35355339059327379f},
  { 0.27778511650980114f,-0.49039264020161522f, 0.09754516100806417f, 0.41573480615127262f,
   -0.41573480615127262f,-0.09754516100806417f, 0.49039264020161522f,-0.27778511650980114f},
  { 0.19134171618254492f,-0.46193976625564337f, 0.46193976625564337f,-0.19134171618254492f,
   -0.19134171618254492f, 0.46193976625564337f,-0.46193976625564337f, 0.19134171618254492f},
  { 0.09754516100806417f,-0.27778511650980114f, 0.41573480615127262f,-0.49039264020161522f,
    0.49039264020161522f,-0.41573480615127262f, 0.27778511650980114f,-0.09754516100806417f}
};

__constant__ float QYc[64] = {
  16,11,10,16,24,40,51,61,
  12,12,14,19,26,58,60,55,
  14,13,16,24,40,57,69,56,
  14,17,22,29,51,87,80,62,
  18,22,37,56,68,109,103,77,
  24,35,55,64,81,104,113,92,
  49,64,78,87,103,121,120,101,
  72,92,95,98,112,100,103,99
};
__constant__ float QCc[64] = {
  17,18,24,47,99,99,99,99,
  18,21,26,66,99,99,99,99,
  24,26,56,99,99,99,99,99,
  47,66,99,99,99,99,99,99,
  99,99,99,99,99,99,99,99,
  99,99,99,99,99,99,99,99,
  99,99,99,99,99,99,99,99,
  99,99,99,99,99,99,99,99
};

#define QFACTOR 0.5f

// Forward 8-pt DCT with even/odd fold. 8 ADD + 32 FMA.
#define DCT_FWD_FOLD(in8, out8)                                            \
  {                                                                        \
    float e_[4], o_[4];                                                    \
    _Pragma("unroll")                                                      \
    for (int j_ = 0; j_ < 4; ++j_) {                                       \
      e_[j_] = in8[j_] + in8[7 - j_];                                      \
      o_[j_] = in8[j_] - in8[7 - j_];                                      \
    }                                                                      \
    _Pragma("unroll")                                                      \
    for (int v_ = 0; v_ < 8; v_ += 2) {                                    \
      float se_ = 0.f, so_ = 0.f;                                          \
      _Pragma("unroll")                                                    \
      for (int j_ = 0; j_ < 4; ++j_) {                                     \
        se_ += D8[v_][j_] * e_[j_];                                        \
        so_ += D8[v_ + 1][j_] * o_[j_];                                    \
      }                                                                    \
      out8[v_] = se_; out8[v_ + 1] = so_;                                  \
    }                                                                      \
  }

// Inverse 8-pt DCT with fold. 32 FMA + 8 ADD.
#define DCT_INV_FOLD(w8, rec8)                                             \
  {                                                                        \
    _Pragma("unroll")                                                      \
    for (int j_ = 0; j_ < 4; ++j_) {                                       \
      float E_ = 0.f, O_ = 0.f;                                            \
      _Pragma("unroll")                                                    \
      for (int v_ = 0; v_ < 8; v_ += 2) {                                  \
        E_ += D8[v_][j_] * w8[v_];                                         \
        O_ += D8[v_ + 1][j_] * w8[v_ + 1];                                 \
      }                                                                    \
      rec8[j_] = E_ + O_; rec8[7 - j_] = E_ - O_;                          \
    }                                                                      \
  }

// Tile: 32 rows x 32 cols, 256 threads. 24 blocks of 8x8 in shared scratch:
//   blk 0..15  : Y   (blk = (row>>3)*4 + (col>>3))
//   blk 16..19 : Cb  (16x16 downsampled), blk 20..23 : Cr
// s[blk*72 + x*9 + y]: conflict-free for both access orientations.

__global__ __launch_bounds__(256, 8) void diffjpeg_kernel(
    const float* __restrict__ x, float* __restrict__ out)
{
    __shared__ float s[24 * 72];
    __shared__ float2 qYp[64], qCp[64];   // (q, 1/q)

    const int tid = threadIdx.x;
    if (tid < 64) {
        const float a = QYc[tid] * QFACTOR;
        const float b = QCc[tid] * QFACTOR;
        qYp[tid] = make_float2(a, 1.0f / a);
        qCp[tid] = make_float2(b, 1.0f / b);
    }

    const int bz = blockIdx.z;
    const int tr = blockIdx.y;
    const int tc = blockIdx.x;
    const size_t plane4 = 512 * 512 / 4;
    const float4* px4 = (const float4*)x + (size_t)bz * 3 * plane4 + (size_t)(tr * 32) * 128 + tc * 8;
    float4*       po4 = (float4*)out     + (size_t)bz * 3 * plane4 + (size_t)(tr * 32) * 128 + tc * 8;

    const int row = tid >> 3;   // 0..31
    const int cg  = tid & 7;    // 0..7 -> cols 4cg..4cg+3
    const bool hi = (cg & 1);   // which half of the 8-col block this thread owns
    const int yblk = (row >> 3) * 4 + (cg >> 1);
    float* bYv = s + yblk * 72 + (row & 7) * 9;   // block row base (freq index appended)

    // ---- Phase 1: load, clip, RGB->YCbCr, Y forward-y DCT (regs+shfl),
    //      chroma 2x2 downsample ----
    {
        const float4 R4 = px4[(size_t)row * 128 + cg];
        const float4 G4 = px4[plane4 + (size_t)row * 128 + cg];
        const float4 B4 = px4[2 * plane4 + (size_t)row * 128 + cg];
        float rr[4] = {R4.x, R4.y, R4.z, R4.w};
        float gg[4] = {G4.x, G4.y, G4.z, G4.w};
        float bb[4] = {B4.x, B4.y, B4.z, B4.w};
        float yv[4], cbv[4], crv[4];
        #pragma unroll
        for (int j = 0; j < 4; ++j) {
            const float r1 = fminf(fmaxf(rr[j], 0.f), 1.f) * 255.f;
            const float g1 = fminf(fmaxf(gg[j], 0.f), 1.f) * 255.f;
            const float b1 = fminf(fmaxf(bb[j], 0.f), 1.f) * 255.f;
            yv[j] = 0.299f * r1 + 0.587f * g1 + 0.114f * b1 - 128.f;
            cbv[j] = -0.168736f * r1 - 0.331264f * g1 + 0.5f * b1;
            crv[j] =  0.5f * r1 - 0.418688f * g1 - 0.081312f * b1;
        }
        // gather the full 8-pixel block row: partner is lane^1 (same row, cg^1)
        float ov[4];
        #pragma unroll
        for (int j = 0; j < 4; ++j) ov[j] = __shfl_xor_sync(0xffffffffu, yv[j], 1);
        float in8[8];
        #pragma unroll
        for (int j = 0; j < 4; ++j) {
            in8[j]     = hi ? ov[j] : yv[j];
            in8[4 + j] = hi ? yv[j] : ov[j];
        }
        float out8[8];
        DCT_FWD_FOLD(in8, out8);
        #pragma unroll
        for (int j = 0; j < 4; ++j)
            bYv[(hi ? 4 : 0) + j] = hi ? out8[4 + j] : out8[j];

        // chroma: horizontal pair in-thread, vertical pair via shfl xor 8
        // (row = tid>>3 -> rows r, r^1 are lanes L, L^8 in the same warp)
        float cbh[2] = {cbv[0] + cbv[1], cbv[2] + cbv[3]};
        float crh[2] = {crv[0] + crv[1], crv[2] + crv[3]};
        #pragma unroll
        for (int k = 0; k < 2; ++k) {
            cbh[k] += __shfl_xor_sync(0xffffffffu, cbh[k], 8);
            crh[k] += __shfl_xor_sync(0xffffffffu, crh[k], 8);
        }
        if ((row & 1) == 0) {
            const int crow = row >> 1;            // 0..15
            const int base = (crow & 7) * 9;
            #pragma unroll
            for (int k = 0; k < 2; ++k) {
                const int ccol = 2 * cg + k;      // 0..15
                const int cblk = 16 + (crow >> 3) * 2 + (ccol >> 3);
                s[cblk * 72 + base + (ccol & 7)]       = 0.25f * cbh[k];
                s[(cblk + 4) * 72 + base + (ccol & 7)] = 0.25f * crh[k];
            }
        }
    }
    __syncthreads();

    // ---- Region 2: Y pass-B on threads 0..127; chroma chain on 128..255 ----
    if (tid < 128) {
        // Y blocks: 16 blocks x 8 columns = 128 units
        const int blk = tid >> 3, v = tid & 7;
        float* bp = s + blk * 72 + v;
        float t[8];
        #pragma unroll
        for (int xx = 0; xx < 8; ++xx) t[xx] = bp[xx * 9];
        float cf[8];
        DCT_FWD_FOLD(t, cf);
        #pragma unroll
        for (int u = 0; u < 8; ++u) {
            const float2 qq = qYp[u * 8 + v];
            cf[u] = rintf(cf[u] * qq.y) * qq.x;   // round-half-even
        }
        float w[8];
        DCT_INV_FOLD(cf, w);
        #pragma unroll
        for (int xx = 0; xx < 8; ++xx) bp[xx * 9] = w[xx];
    } else {
        const int u = tid - 128;   // 0..127; chroma = 8 blocks x 8 = 64 units
        // (a) chroma forward DCT along y (stride-1 rows)
        if (u < 64) {
            const int blk = 16 + (u >> 3), xx = u & 7;
            float* bp = s + blk * 72 + xx * 9;
            float in8[8];
            #pragma unroll
            for (int j = 0; j < 8; ++j) in8[j] = bp[j];
            float out8[8];
            DCT_FWD_FOLD(in8, out8);
            #pragma unroll
            for (int j = 0; j < 8; ++j) bp[j] = out8[j];
        }
        asm volatile("bar.sync 1, 128;" ::: "memory");
        // (b) chroma pass-B along x (stride-9)
        if (u < 64) {
            const int blk = 16 + (u >> 3), v = u & 7;
            float* bp = s + blk * 72 + v;
            float t[8];
            #pragma unroll
            for (int xx = 0; xx < 8; ++xx) t[xx] = bp[xx * 9];
            float cf[8];
            DCT_FWD_FOLD(t, cf);
            #pragma unroll
            for (int uu = 0; uu < 8; ++uu) {
                const float2 qq = qCp[uu * 8 + v];
                cf[uu] = rintf(cf[uu] * qq.y) * qq.x;
            }
            float w[8];
            DCT_INV_FOLD(cf, w);
            #pragma unroll
            for (int xx = 0; xx < 8; ++xx) bp[xx * 9] = w[xx];
        }
        asm volatile("bar.sync 1, 128;" ::: "memory");
        // (c) chroma inverse DCT along y
        if (u < 64) {
            const int blk = 16 + (u >> 3), xx = u & 7;
            float* bp = s + blk * 72 + xx * 9;
            float w[8];
            #pragma unroll
            for (int v = 0; v < 8; ++v) w[v] = bp[v];
            float rec[8];
            DCT_INV_FOLD(w, rec);
            #pragma unroll
            for (int j = 0; j < 8; ++j) bp[j] = rec[j];
        }
    }
    __syncthreads();

    // ---- Output: inverse-y for Y in registers + chroma upsample + store ----
    {
        float w[8];
        #pragma unroll
        for (int v = 0; v < 8; ++v) w[v] = bYv[v];
        float E[4], O[4];
        #pragma unroll
        for (int j = 0; j < 4; ++j) {
            float Ee = 0.f, Oo = 0.f;
            #pragma unroll
            for (int v = 0; v < 8; v += 2) {
                Ee += D8[v][j] * w[v];
                Oo += D8[v + 1][j] * w[v + 1];
            }
            E[j] = Ee; O[j] = Oo;
        }
        float yrec[4];
        #pragma unroll
        for (int j = 0; j < 4; ++j)
            yrec[j] = hi ? (E[3 - j] - O[3 - j]) : (E[j] + O[j]);

        const int crow = row >> 1;
        const int base = (crow & 7) * 9;
        const int ccol0 = 2 * cg;
        const int cblk = 16 + (crow >> 3) * 2 + (ccol0 >> 3);
        const float cb0 = s[cblk * 72 + base + (ccol0 & 7)];
        const float cb1 = s[cblk * 72 + base + (ccol0 & 7) + 1];
        const float cr0 = s[(cblk + 4) * 72 + base + (ccol0 & 7)];
        const float cr1 = s[(cblk + 4) * 72 + base + (ccol0 & 7) + 1];
        const float cbm[4] = {cb0, cb0, cb1, cb1};
        const float crm[4] = {cr0, cr0, cr1, cr1};
        float R[4], G[4], B[4];
        #pragma unroll
        for (int j = 0; j < 4; ++j) {
            const float yv = yrec[j] + 128.f;
            float Rv = yv + 1.402f * crm[j];
            float Gv = yv - 0.344136f * cbm[j] - 0.714136f * crm[j];
            float Bv = yv + 1.772f * cbm[j];
            R[j] = fminf(fmaxf(Rv, 0.f), 255.f) * (1.0f / 255.0f);
            G[j] = fminf(fmaxf(Gv, 0.f), 255.f) * (1.0f / 255.0f);
            B[j] = fminf(fmaxf(Bv, 0.f), 255.f) * (1.0f / 255.0f);
        }
        const size_t o = (size_t)row * 128 + cg;
        po4[o]              = make_float4(R[0], R[1], R[2], R[3]);
        po4[plane4 + o]     = make_float4(G[0], G[1], G[2], G[3]);
        po4[2 * plane4 + o] = make_float4(B[0], B[1], B[2], B[3]);
    }
}

extern "C" void kernel_launch(void* const* d_in, const int* in_sizes, int n_in,
                              void* d_out, int out_size)
{
    const float* x = (const float*)d_in[0];
    float* out = (float*)d_out;
    (void)in_sizes; (void)n_in; (void)out_size;
    dim3 grid(16, 16, 16);   // tile cols (512/32), tile rows (512/32), batch
    diffjpeg_kernel<<<grid, 256>>>(x, out);
}